// round 1
// baseline (speedup 1.0000x reference)
#include <cuda_runtime.h>

#define BB 256
#define TT 200
#define QQ 1024
#define NROWS (BB * (TT - 1))   // 50944 (b, t) pairs with t in [1, T-1]

// Scratch for deterministic two-stage reduction (no allocations allowed).
__device__ float g_partials[NROWS];

// One CTA per (b, t) row: scan batch[b, t, 0:2Q] (8KB), find the one-hot
// delta entry, gather the single needed pred element, emit the BCE term.
__global__ __launch_bounds__(256) void loss_row_kernel(
    const float* __restrict__ pred,
    const float* __restrict__ batch)
{
    const int n   = blockIdx.x;
    const int b   = n / (TT - 1);
    const int t   = n % (TT - 1) + 1;       // delta/answers index (1..T-1)
    const int tid = threadIdx.x;

    const float4* row = reinterpret_cast<const float4*>(
        batch + ((size_t)b * TT + t) * (size_t)(2 * QQ));

    // pos half: float4 index [0, 256), neg half: [256, 512)
    float4 pos = row[tid];
    float4 neg = row[tid + QQ / 4];

    // partial of sum(pos - neg)  (exact: entries are 0.0 or 1.0)
    float diff = (pos.x + pos.y + pos.z + pos.w)
               - (neg.x + neg.y + neg.z + neg.w);

    // delta = pos + neg (one-hot): detect the unique nonzero component
    float d0 = pos.x + neg.x, d1 = pos.y + neg.y;
    float d2 = pos.z + neg.z, d3 = pos.w + neg.w;

    __shared__ int   s_q;
    __shared__ float s_dval;
    __shared__ float s_diff[8];

    if (tid == 0) s_q = -1;
    __syncthreads();

    // Exactly one thread (at most) writes — race-free by construction.
    if (d0 != 0.0f) { s_q = tid * 4 + 0; s_dval = d0; }
    if (d1 != 0.0f) { s_q = tid * 4 + 1; s_dval = d1; }
    if (d2 != 0.0f) { s_q = tid * 4 + 2; s_dval = d2; }
    if (d3 != 0.0f) { s_q = tid * 4 + 3; s_dval = d3; }

    // block reduction of diff (warp shuffle + smem)
    #pragma unroll
    for (int o = 16; o > 0; o >>= 1)
        diff += __shfl_xor_sync(0xffffffffu, diff, o);
    if ((tid & 31) == 0) s_diff[tid >> 5] = diff;
    __syncthreads();

    if (tid == 0) {
        float dsum = 0.0f;
        #pragma unroll
        for (int w = 0; w < 8; w++) dsum += s_diff[w];

        // answers = floor((sum(pos - neg) + 1) / 2)
        float a = floorf((dsum + 1.0f) * 0.5f);

        // probs = delta . pred[b, t-1, :]  == delta_val * pred[b, t-1, q]
        float probs = 0.0f;
        if (s_q >= 0)
            probs = s_dval * __ldg(&pred[((size_t)b * TT + (t - 1)) * QQ + s_q]);

        float contrib = 0.0f;
        if (probs > 0.0f) {
            float ll = a * logf(probs) + (1.0f - a) * log1pf(-probs);
            contrib = -ll;                 // where(mask, ll, 0), negated
        }
        g_partials[n] = contrib;
    }
}

// Deterministic final reduction: fixed grid-stride order + smem tree.
__global__ __launch_bounds__(1024) void loss_reduce_kernel(float* __restrict__ out)
{
    __shared__ float s[1024];
    const int tid = threadIdx.x;
    float sum = 0.0f;
    for (int i = tid; i < NROWS; i += 1024)
        sum += g_partials[i];
    s[tid] = sum;
    __syncthreads();
    #pragma unroll
    for (int o = 512; o > 0; o >>= 1) {
        if (tid < o) s[tid] += s[tid + o];
        __syncthreads();
    }
    if (tid == 0) out[0] = s[0];
}

extern "C" void kernel_launch(void* const* d_in, const int* in_sizes, int n_in,
                              void* d_out, int out_size)
{
    const float* pred  = (const float*)d_in[0];
    const float* batch = (const float*)d_in[1];
    // pred has B*T*Q elems, batch has B*T*2Q — order-proof via sizes.
    if (n_in >= 2 && in_sizes[0] > in_sizes[1]) {
        const float* tmp = pred; pred = batch; batch = tmp;
    }

    loss_row_kernel<<<NROWS, 256>>>(pred, batch);
    loss_reduce_kernel<<<1, 1024>>>((float*)d_out);
}

// round 2
// speedup vs baseline: 1.0004x; 1.0004x over previous
#include <cuda_runtime.h>

#define BB 256
#define TT 200
#define QQ 1024
#define NROWS (BB * (TT - 1))    // 50944 rows (t = 1..199)
#define NCTA  1184               // 148 SMs * 8 CTAs

// Per-CTA partials for deterministic two-stage reduction (no allocs allowed).
__device__ float g_partials[NCTA];

// Persistent CTAs. Per row: scan pos half (4KB). The one-hot hit's half
// encodes the answer a (pos half -> a=1, neg half -> a=0) and its value is
// exactly 1.0, so probs = pred[b, t-1, q]. Only scan the neg half when the
// pos half is empty (~50% of rows) => ~313MB total traffic vs 417MB.
__global__ __launch_bounds__(256) void loss_row_kernel(
    const float* __restrict__ pred,
    const float* __restrict__ batch)
{
    const int tid = threadIdx.x;
    __shared__ int s_q;

    float acc = 0.0f;

    for (int n = blockIdx.x; n < NROWS; n += NCTA) {
        const int b = n / (TT - 1);
        const int t = n % (TT - 1) + 1;

        const float4* row = reinterpret_cast<const float4*>(
            batch + ((size_t)b * TT + t) * (size_t)(2 * QQ));

        if (tid == 0) s_q = -1;
        __syncthreads();

        // --- pos half: 256 threads x float4 = 4KB, streaming loads ---
        float4 v = __ldcs(&row[tid]);
        int q = -1;
        if      (v.x != 0.0f) q = tid * 4 + 0;
        else if (v.y != 0.0f) q = tid * 4 + 1;
        else if (v.z != 0.0f) q = tid * 4 + 2;
        else if (v.w != 0.0f) q = tid * 4 + 3;
        if (q >= 0) s_q = q;            // at most one writer: race-free
        __syncthreads();

        float a  = 1.0f;
        int   qq = s_q;                  // uniform across block

        if (qq < 0) {
            // --- neg half only when pos half was empty ---
            float4 w = __ldcs(&row[tid + QQ / 4]);
            int q2 = -1;
            if      (w.x != 0.0f) q2 = tid * 4 + 0;
            else if (w.y != 0.0f) q2 = tid * 4 + 1;
            else if (w.z != 0.0f) q2 = tid * 4 + 2;
            else if (w.w != 0.0f) q2 = tid * 4 + 3;
            if (q2 >= 0) s_q = q2;
            __syncthreads();
            a  = 0.0f;
            qq = s_q;
        }

        if (tid == 0 && qq >= 0) {
            // delta value is exactly 1.0 => probs = pred[b, t-1, qq]
            float p = __ldg(&pred[((size_t)b * TT + (t - 1)) * QQ + qq]);
            if (p > 0.0f)
                acc -= (a > 0.5f) ? logf(p) : log1pf(-p);
        }
        __syncthreads();   // protect s_q reuse across iterations
    }

    if (tid == 0) g_partials[blockIdx.x] = acc;
}

// Tiny deterministic reduction of NCTA partials (L2-hot, ~2us).
__global__ __launch_bounds__(256) void loss_reduce_kernel(float* __restrict__ out)
{
    __shared__ float s[256];
    const int tid = threadIdx.x;
    float sum = 0.0f;
    for (int i = tid; i < NCTA; i += 256)
        sum += g_partials[i];
    s[tid] = sum;
    __syncthreads();
    #pragma unroll
    for (int o = 128; o > 0; o >>= 1) {
        if (tid < o) s[tid] += s[tid + o];
        __syncthreads();
    }
    if (tid == 0) out[0] = s[0];
}

extern "C" void kernel_launch(void* const* d_in, const int* in_sizes, int n_in,
                              void* d_out, int out_size)
{
    const float* pred  = (const float*)d_in[0];
    const float* batch = (const float*)d_in[1];
    if (n_in >= 2 && in_sizes[0] > in_sizes[1]) {
        const float* tmp = pred; pred = batch; batch = tmp;
    }

    loss_row_kernel<<<NCTA, 256>>>(pred, batch);
    loss_reduce_kernel<<<1, 256>>>((float*)d_out);
}

// round 4
// speedup vs baseline: 1.3248x; 1.3242x over previous
#include <cuda_runtime.h>

#define BB 256
#define TT 200
#define QQ 1024
#define NROWS (BB * (TT - 1))     // 50944 rows (t = 1..199)
#define NCTA  1184                // 148 SMs * 8 CTAs of 256 threads
#define WPC   8                   // warps per CTA
#define NWARP (NCTA * WPC)        // 9472 warps, ~5.4 rows each

__device__ float        g_partials[NCTA];
__device__ unsigned int g_done = 0;   // reset by last CTA each run (replay-safe)

// Warp-per-row: lane loads 8 float4 (128B) from the pos half -> MLP=8,
// ballot to find the one-hot hit (its half encodes the answer a, value is
// exactly 1.0). Only scan the neg half when pos half is empty (~50%).
// No block barriers in the hot loop; warps pipeline independently.
__global__ __launch_bounds__(256) void loss_kernel(
    const float* __restrict__ pred,
    const float* __restrict__ batch,
    float* __restrict__ out)
{
    const int tid  = threadIdx.x;
    const int lane = tid & 31;
    const int wid  = tid >> 5;

    __shared__ float s_acc[WPC];
    __shared__ float s_red[256];
    __shared__ int   s_last;

    float acc = 0.0f;

    for (int n = blockIdx.x * WPC + wid; n < NROWS; n += NWARP) {
        const int b = n / (TT - 1);
        const int t = n % (TT - 1) + 1;

        const float4* row4 = reinterpret_cast<const float4*>(
            batch + ((size_t)b * TT + t) * (size_t)(2 * QQ));

        // ---- pos half: 8 coalesced float4 loads per lane (4KB/warp) ----
        float4 v[8];
        #pragma unroll
        for (int i = 0; i < 8; i++) v[i] = row4[lane + 32 * i];

        int q = -1;
        #pragma unroll
        for (int i = 0; i < 8; i++) {
            const int base = (lane + 32 * i) * 4;
            if      (v[i].x != 0.0f) q = base + 0;
            else if (v[i].y != 0.0f) q = base + 1;
            else if (v[i].z != 0.0f) q = base + 2;
            else if (v[i].w != 0.0f) q = base + 3;
        }

        unsigned bal = __ballot_sync(0xffffffffu, q >= 0);
        float a = 1.0f;

        if (!bal) {
            // ---- neg half only if pos half empty ----
            #pragma unroll
            for (int i = 0; i < 8; i++) v[i] = row4[QQ / 4 + lane + 32 * i];
            #pragma unroll
            for (int i = 0; i < 8; i++) {
                const int base = (lane + 32 * i) * 4;
                if      (v[i].x != 0.0f) q = base + 0;
                else if (v[i].y != 0.0f) q = base + 1;
                else if (v[i].z != 0.0f) q = base + 2;
                else if (v[i].w != 0.0f) q = base + 3;
            }
            bal = __ballot_sync(0xffffffffu, q >= 0);
            a = 0.0f;
        }

        if (bal) {
            const int src = __ffs(bal) - 1;
            const int qq  = __shfl_sync(0xffffffffu, q, src);
            if (lane == 0) {
                // delta value is exactly 1.0 => probs = pred[b, t-1, qq]
                const float p = __ldg(&pred[((size_t)b * TT + (t - 1)) * QQ + qq]);
                if (p > 0.0f)
                    acc -= (a > 0.5f) ? logf(p) : log1pf(-p);
            }
        }
    }

    // ---- CTA partial ----
    if (lane == 0) s_acc[wid] = acc;
    __syncthreads();

    if (tid == 0) {
        float partial = 0.0f;
        #pragma unroll
        for (int i = 0; i < WPC; i++) partial += s_acc[i];
        g_partials[blockIdx.x] = partial;
        __threadfence();
        const unsigned old = atomicAdd(&g_done, 1u);
        s_last = (old == NCTA - 1);
    }
    __syncthreads();

    // ---- last CTA performs the deterministic final reduction ----
    if (s_last) {
        if (tid == 0) g_done = 0;        // reset for next graph replay
        __threadfence();
        float s = 0.0f;
        for (int i = tid; i < NCTA; i += 256) s += g_partials[i];
        s_red[tid] = s;
        __syncthreads();
        #pragma unroll
        for (int o = 128; o > 0; o >>= 1) {
            if (tid < o) s_red[tid] += s_red[tid + o];
            __syncthreads();
        }
        if (tid == 0) out[0] = s_red[0];
    }
}

extern "C" void kernel_launch(void* const* d_in, const int* in_sizes, int n_in,
                              void* d_out, int out_size)
{
    const float* pred  = (const float*)d_in[0];
    const float* batch = (const float*)d_in[1];
    if (n_in >= 2 && in_sizes[0] > in_sizes[1]) {
        const float* tmp = pred; pred = batch; batch = tmp;
    }

    loss_kernel<<<NCTA, 256>>>(pred, batch, (float*)d_out);
}

// round 5
// speedup vs baseline: 1.3750x; 1.0379x over previous
#include <cuda_runtime.h>

#define BB 256
#define TT 200
#define QQ 1024
#define NROWS (BB * (TT - 1))     // 50944 rows (t = 1..199)
#define NCTA  1184                // 148 SMs * 8 CTAs of 256 threads
#define WPC   8
#define NWARP (NCTA * WPC)        // 9472 warps
#define RPW   6                   // ceil(NROWS / NWARP) rows per warp

#define MISS_BIT (1 << 16)

__device__ float        g_partials[NCTA];
__device__ unsigned int g_done = 0;   // reset by last CTA each run (replay-safe)

// Scan one 4KB half-row (256 float4) with a full warp: 8 independent 16B
// streaming loads per lane, then locate the unique nonzero element.
// Returns its index in [0,1024) broadcast to all lanes, or -1 if all-zero.
__device__ __forceinline__ int scan_half(const float4* __restrict__ base, int lane)
{
    uint4 v[8];
    #pragma unroll
    for (int i = 0; i < 8; i++)
        v[i] = __ldcs(reinterpret_cast<const uint4*>(base) + lane + 32 * i);

    int q = -1;
    #pragma unroll
    for (int i = 0; i < 8; i++) {
        const int b4 = (lane + 32 * i) * 4;
        if      (v[i].x) q = b4 + 0;
        else if (v[i].y) q = b4 + 1;
        else if (v[i].z) q = b4 + 2;
        else if (v[i].w) q = b4 + 3;
    }
    const unsigned bal = __ballot_sync(0xffffffffu, q >= 0);
    if (bal == 0u) return -1;
    return __shfl_sync(0xffffffffu, q, __ffs(bal) - 1);
}

__global__ __launch_bounds__(256) void loss_kernel(
    const float* __restrict__ pred,
    const float* __restrict__ batch,
    float* __restrict__ out)
{
    const int tid  = threadIdx.x;
    const int lane = tid & 31;
    const int wid  = tid >> 5;
    const int w0   = blockIdx.x * WPC + wid;   // global warp id

    __shared__ float s_acc[WPC];
    __shared__ float s_red[256];
    __shared__ int   s_last;

    // qa[k]: -2 invalid row | -1 unresolved | q (a=1) | q|MISS_BIT (a=0)
    int qa[RPW];

    // ---- Phase A: stream pos halves of all my rows (pure bursts) ----
    #pragma unroll
    for (int k = 0; k < RPW; k++) {
        const int n = w0 + k * NWARP;
        if (n >= NROWS) { qa[k] = -2; continue; }
        const int b = n / (TT - 1);
        const int t = n % (TT - 1) + 1;
        const float4* row = reinterpret_cast<const float4*>(
            batch + ((size_t)b * TT + t) * (size_t)(2 * QQ));
        qa[k] = scan_half(row, lane);          // >=0 hit (a=1), -1 miss
    }

    // ---- Phase B: neg halves only for miss rows ----
    #pragma unroll
    for (int k = 0; k < RPW; k++) {
        if (qa[k] == -1) {
            const int n = w0 + k * NWARP;
            const int b = n / (TT - 1);
            const int t = n % (TT - 1) + 1;
            const float4* row = reinterpret_cast<const float4*>(
                batch + ((size_t)b * TT + t) * (size_t)(2 * QQ));
            const int q = scan_half(row + QQ / 4, lane);
            if (q >= 0) qa[k] = q | MISS_BIT;  // a=0
        }
    }

    // ---- Phase C: lanes 0..5 gather pred in parallel (MLP=6, one RT) ----
    int myqa = -2;
    #pragma unroll
    for (int k = 0; k < RPW; k++)
        if (lane == k) myqa = qa[k];

    float c = 0.0f;
    if (myqa >= 0) {
        const int n = w0 + lane * NWARP;       // lane == k here
        const int b = n / (TT - 1);
        const int t = n % (TT - 1) + 1;
        const int q = myqa & 0xFFFF & ~MISS_BIT;
        const float p = __ldg(&pred[((size_t)b * TT + (t - 1)) * QQ + (myqa & 0x3FF)]);
        if (p > 0.0f)
            c = (myqa & MISS_BIT) ? -log1pf(-p) : -logf(p);
        (void)q;
    }

    // warp-reduce the up-to-6 contributions
    #pragma unroll
    for (int o = 16; o > 0; o >>= 1)
        c += __shfl_xor_sync(0xffffffffu, c, o);

    if (lane == 0) s_acc[wid] = c;
    __syncthreads();

    if (tid == 0) {
        float partial = 0.0f;
        #pragma unroll
        for (int i = 0; i < WPC; i++) partial += s_acc[i];
        g_partials[blockIdx.x] = partial;
        __threadfence();
        const unsigned old = atomicAdd(&g_done, 1u);
        s_last = (old == NCTA - 1);
    }
    __syncthreads();

    // ---- last CTA: deterministic final reduction + counter reset ----
    if (s_last) {
        if (tid == 0) g_done = 0;
        __threadfence();
        float s = 0.0f;
        for (int i = tid; i < NCTA; i += 256) s += g_partials[i];
        s_red[tid] = s;
        __syncthreads();
        #pragma unroll
        for (int o = 128; o > 0; o >>= 1) {
            if (tid < o) s_red[tid] += s_red[tid + o];
            __syncthreads();
        }
        if (tid == 0) out[0] = s_red[0];
    }
}

extern "C" void kernel_launch(void* const* d_in, const int* in_sizes, int n_in,
                              void* d_out, int out_size)
{
    const float* pred  = (const float*)d_in[0];
    const float* batch = (const float*)d_in[1];
    if (n_in >= 2 && in_sizes[0] > in_sizes[1]) {
        const float* tmp = pred; pred = batch; batch = tmp;
    }

    loss_kernel<<<NCTA, 256>>>(pred, batch, (float*)d_out);
}